// round 1
// baseline (speedup 1.0000x reference)
#include <cuda_runtime.h>

#define B_ 16
#define T_ 2048
#define E_ 1024
#define H_ 128
#define M_ (B_*T_)

// Scratch for projected Q/K/V (device globals: allocation-free per harness rules)
__device__ float g_Q[(size_t)M_ * H_];
__device__ float g_K[(size_t)M_ * H_];
__device__ float g_V[(size_t)M_ * H_];

// ---------------------------------------------------------------------------
// Kernel 1: QKV projection GEMM.  C[M,128] = x[M,1024] @ W[1024,128]
// BM=128, BN=128, BK=16, 256 threads, 8x8 micro-tile per thread.
// grid = (M/128, 3): blockIdx.y selects {Wq->Q, Wk->K, Wv->V}
// ---------------------------------------------------------------------------
__global__ __launch_bounds__(256) void qkv_gemm(
    const float* __restrict__ x, const float* __restrict__ Wk,
    const float* __restrict__ Wq, const float* __restrict__ Wv)
{
    __shared__ float Ast[16][132];   // A tile transposed [k][m], padded
    __shared__ float Ws[16][128];    // W tile [k][n]

    const float* W;
    float* D;
    if (blockIdx.y == 0)      { W = Wq; D = g_Q; }
    else if (blockIdx.y == 1) { W = Wk; D = g_K; }
    else                      { W = Wv; D = g_V; }

    const int tid = threadIdx.x;
    const int rowBase = blockIdx.x * 128;
    const int tm = tid >> 4;       // 0..15 -> 8 rows each
    const int tn = tid & 15;       // 0..15 -> 8 cols each

    float acc[8][8];
    #pragma unroll
    for (int i = 0; i < 8; i++)
        #pragma unroll
        for (int j = 0; j < 8; j++) acc[i][j] = 0.f;

    for (int k0 = 0; k0 < E_; k0 += 16) {
        #pragma unroll
        for (int u = 0; u < 2; u++) {
            int i = tid + u * 256;               // 0..511
            int r = i >> 2, kq = i & 3;          // A: 128 rows x 4 float4s
            float4 f = *(const float4*)(x + (size_t)(rowBase + r) * E_ + k0 + kq * 4);
            Ast[kq*4+0][r] = f.x; Ast[kq*4+1][r] = f.y;
            Ast[kq*4+2][r] = f.z; Ast[kq*4+3][r] = f.w;
            int kr = i >> 5, c = (i & 31) * 4;   // W: 16 rows x 32 float4s
            *(float4*)(&Ws[kr][c]) = *(const float4*)(W + (size_t)(k0 + kr) * H_ + c);
        }
        __syncthreads();

        #pragma unroll
        for (int k = 0; k < 16; k++) {
            float4 a0 = *(const float4*)(&Ast[k][tm*8]);
            float4 a1 = *(const float4*)(&Ast[k][tm*8+4]);
            float4 b0 = *(const float4*)(&Ws[k][tn*8]);
            float4 b1 = *(const float4*)(&Ws[k][tn*8+4]);
            float a[8] = {a0.x,a0.y,a0.z,a0.w,a1.x,a1.y,a1.z,a1.w};
            float b[8] = {b0.x,b0.y,b0.z,b0.w,b1.x,b1.y,b1.z,b1.w};
            #pragma unroll
            for (int i = 0; i < 8; i++)
                #pragma unroll
                for (int j = 0; j < 8; j++)
                    acc[i][j] += a[i] * b[j];
        }
        __syncthreads();
    }

    #pragma unroll
    for (int i = 0; i < 8; i++) {
        size_t row = (size_t)rowBase + tm*8 + i;
        float4 o0 = make_float4(acc[i][0], acc[i][1], acc[i][2], acc[i][3]);
        float4 o1 = make_float4(acc[i][4], acc[i][5], acc[i][6], acc[i][7]);
        *(float4*)(D + row * H_ + tn*8)     = o0;
        *(float4*)(D + row * H_ + tn*8 + 4) = o1;
    }
}

// ---------------------------------------------------------------------------
// Kernel 2: causal flash attention, fp32.
// BQ = BK = 64, 256 threads. Thread owns 4 q-rows (tq) x 4 k-cols (tk) for S,
// and the same 4 q-rows x 8 h-cols for O.
// grid = (T/64, B); qtile mapped descending for load balance.
// ---------------------------------------------------------------------------
#define QLD 132
#define PLD 68
#define ATTN_SMEM_FLOATS (3*64*QLD + 64*PLD)

__global__ __launch_bounds__(256) void attn_kernel(float* __restrict__ out)
{
    extern __shared__ float sm[];
    float* Qs = sm;
    float* Ks = Qs + 64*QLD;
    float* Vs = Ks + 64*QLD;
    float* Ps = Vs + 64*QLD;

    const int b  = blockIdx.y;
    const int qt = (int)gridDim.x - 1 - (int)blockIdx.x;  // heavy blocks first
    const int q0 = qt * 64;
    const int tid = threadIdx.x;
    const int tq = tid >> 4;   // 0..15
    const int tk = tid & 15;   // 0..15
    const float scale = 0.08838834764831845f;   // 128^-0.5

    // Load Q tile (pre-scaled)
    #pragma unroll
    for (int u = 0; u < 8; u++) {
        int i = tid + u * 256;            // float4 index 0..2047
        int r = i >> 5, c4 = i & 31;
        float4 f = *(const float4*)(g_Q + ((size_t)b*T_ + q0 + r) * H_ + c4*4);
        f.x *= scale; f.y *= scale; f.z *= scale; f.w *= scale;
        *(float4*)(&Qs[r*QLD + c4*4]) = f;
    }

    float m_i[4], l_i[4], acc[4][8];
    #pragma unroll
    for (int i = 0; i < 4; i++) {
        m_i[i] = -1e30f; l_i[i] = 0.f;
        #pragma unroll
        for (int j = 0; j < 8; j++) acc[i][j] = 0.f;
    }

    for (int kt = 0; kt <= qt; kt++) {
        __syncthreads();   // protect Ks/Vs/Ps from previous iteration readers
        const int k0 = kt * 64;
        #pragma unroll
        for (int u = 0; u < 8; u++) {
            int i = tid + u * 256;
            int r = i >> 5, c4 = i & 31;
            size_t g = ((size_t)b*T_ + k0 + r) * H_ + c4*4;
            *(float4*)(&Ks[r*QLD + c4*4]) = *(const float4*)(g_K + g);
            *(float4*)(&Vs[r*QLD + c4*4]) = *(const float4*)(g_V + g);
        }
        __syncthreads();

        // S = Qs @ Ks^T  (4x4 per thread over h=128)
        float s[4][4];
        #pragma unroll
        for (int i = 0; i < 4; i++)
            #pragma unroll
            for (int j = 0; j < 4; j++) s[i][j] = 0.f;

        #pragma unroll 4
        for (int h4 = 0; h4 < 32; h4++) {
            float4 q[4], kk[4];
            #pragma unroll
            for (int i = 0; i < 4; i++)
                q[i] = *(const float4*)(&Qs[(tq*4+i)*QLD + h4*4]);
            #pragma unroll
            for (int j = 0; j < 4; j++)
                kk[j] = *(const float4*)(&Ks[(tk*4+j)*QLD + h4*4]);
            #pragma unroll
            for (int i = 0; i < 4; i++)
                #pragma unroll
                for (int j = 0; j < 4; j++)
                    s[i][j] += q[i].x*kk[j].x + q[i].y*kk[j].y
                             + q[i].z*kk[j].z + q[i].w*kk[j].w;
        }

        if (kt == qt) {   // diagonal tile: causal mask
            #pragma unroll
            for (int i = 0; i < 4; i++)
                #pragma unroll
                for (int j = 0; j < 4; j++)
                    if (tk*4 + j > tq*4 + i) s[i][j] = -1e30f;
        }

        // Online softmax update (reduce across 16 tk-lanes, stride-1 halves of warp)
        #pragma unroll
        for (int i = 0; i < 4; i++) {
            float rmax = fmaxf(fmaxf(s[i][0], s[i][1]), fmaxf(s[i][2], s[i][3]));
            #pragma unroll
            for (int o = 8; o >= 1; o >>= 1)
                rmax = fmaxf(rmax, __shfl_xor_sync(0xffffffffu, rmax, o));
            float mnew  = fmaxf(m_i[i], rmax);
            float alpha = __expf(m_i[i] - mnew);
            float rsum = 0.f;
            #pragma unroll
            for (int j = 0; j < 4; j++) { s[i][j] = __expf(s[i][j] - mnew); rsum += s[i][j]; }
            #pragma unroll
            for (int o = 8; o >= 1; o >>= 1)
                rsum += __shfl_xor_sync(0xffffffffu, rsum, o);
            l_i[i] = l_i[i] * alpha + rsum;
            m_i[i] = mnew;
            *(float4*)(&Ps[(tq*4+i)*PLD + tk*4]) =
                make_float4(s[i][0], s[i][1], s[i][2], s[i][3]);
            #pragma unroll
            for (int j = 0; j < 8; j++) acc[i][j] *= alpha;
        }
        __syncthreads();

        // O += P @ V  (4 rows x 8 h-cols per thread)
        #pragma unroll 4
        for (int j = 0; j < 64; j++) {
            float4 v0 = *(const float4*)(&Vs[j*QLD + tk*8]);
            float4 v1 = *(const float4*)(&Vs[j*QLD + tk*8 + 4]);
            #pragma unroll
            for (int i = 0; i < 4; i++) {
                float p = Ps[(tq*4+i)*PLD + j];
                acc[i][0] += p*v0.x; acc[i][1] += p*v0.y;
                acc[i][2] += p*v0.z; acc[i][3] += p*v0.w;
                acc[i][4] += p*v1.x; acc[i][5] += p*v1.y;
                acc[i][6] += p*v1.z; acc[i][7] += p*v1.w;
            }
        }
    }

    // Epilogue: normalize and write
    #pragma unroll
    for (int i = 0; i < 4; i++) {
        float inv = 1.f / l_i[i];
        size_t row = (size_t)b*T_ + q0 + tq*4 + i;
        float4 o0 = make_float4(acc[i][0]*inv, acc[i][1]*inv, acc[i][2]*inv, acc[i][3]*inv);
        float4 o1 = make_float4(acc[i][4]*inv, acc[i][5]*inv, acc[i][6]*inv, acc[i][7]*inv);
        *(float4*)(out + row * H_ + tk*8)     = o0;
        *(float4*)(out + row * H_ + tk*8 + 4) = o1;
    }
}

// ---------------------------------------------------------------------------
extern "C" void kernel_launch(void* const* d_in, const int* in_sizes, int n_in,
                              void* d_out, int out_size)
{
    const float* x  = (const float*)d_in[0];
    const float* Wk = (const float*)d_in[1];
    const float* Wq = (const float*)d_in[2];
    const float* Wv = (const float*)d_in[3];
    float* out = (float*)d_out;

    dim3 g1(M_ / 128, 3);
    qkv_gemm<<<g1, 256>>>(x, Wk, Wq, Wv);

    size_t smem = (size_t)ATTN_SMEM_FLOATS * sizeof(float);
    cudaFuncSetAttribute(attn_kernel,
                         cudaFuncAttributeMaxDynamicSharedMemorySize, (int)smem);
    dim3 g2(T_ / 64, B_);
    attn_kernel<<<g2, 256, smem>>>(out);
}

// round 5
// speedup vs baseline: 1.0715x; 1.0715x over previous
#include <cuda_runtime.h>
#include <cuda_bf16.h>
#include <cstdint>

#define B_ 16
#define T_ 2048
#define E_ 1024
#define H_ 128
#define M_ (B_*T_)

// ---------------------------------------------------------------------------
// Device scratch (allocation-free per harness rules)
// ---------------------------------------------------------------------------
__device__ float g_Q[(size_t)M_ * H_];
__device__ float g_K[(size_t)M_ * H_];
__device__ float g_V[(size_t)M_ * H_];
// Transposed bf16-split weights: [matrix(Q,K,V)][n=128][k=1024]
__device__ __align__(16) __nv_bfloat16 g_Wt_hi[3][H_][E_];
__device__ __align__(16) __nv_bfloat16 g_Wt_lo[3][H_][E_];

// ---------------------------------------------------------------------------
// Baseline-PTX tensor-core helpers (ldmatrix + mma.sync, sm_80+ ISA)
// ---------------------------------------------------------------------------
__device__ __forceinline__ uint32_t smem_u32(const void* p) {
    uint32_t a;
    asm("{ .reg .u64 t; cvta.to.shared.u64 t, %1; cvt.u32.u64 %0, t; }" : "=r"(a) : "l"(p));
    return a;
}
__device__ __forceinline__ void ldsm_x4(uint32_t* r, uint32_t addr) {
    asm volatile("ldmatrix.sync.aligned.m8n8.x4.shared.b16 {%0,%1,%2,%3}, [%4];"
                 : "=r"(r[0]), "=r"(r[1]), "=r"(r[2]), "=r"(r[3]) : "r"(addr));
}
__device__ __forceinline__ void ldsm_x2(uint32_t* r, uint32_t addr) {
    asm volatile("ldmatrix.sync.aligned.m8n8.x2.shared.b16 {%0,%1}, [%2];"
                 : "=r"(r[0]), "=r"(r[1]) : "r"(addr));
}
__device__ __forceinline__ void mma16816(float* d, const uint32_t* a, const uint32_t* b) {
    asm volatile(
        "mma.sync.aligned.m16n8k16.row.col.f32.bf16.bf16.f32 "
        "{%0,%1,%2,%3}, {%4,%5,%6,%7}, {%8,%9}, {%0,%1,%2,%3};"
        : "+f"(d[0]), "+f"(d[1]), "+f"(d[2]), "+f"(d[3])
        : "r"(a[0]), "r"(a[1]), "r"(a[2]), "r"(a[3]), "r"(b[0]), "r"(b[1]));
}
__device__ __forceinline__ uint32_t pack_bf2(__nv_bfloat16 a, __nv_bfloat16 b) {
    __nv_bfloat162 t = __halves2bfloat162(a, b);
    return *reinterpret_cast<uint32_t*>(&t);
}

// ---------------------------------------------------------------------------
// Kernel 0: weight transpose + bf16 hi/lo split. W[E,H] fp32 -> Wt[H][E] bf16
// ---------------------------------------------------------------------------
__global__ void wsplit_kernel(const float* __restrict__ Wk,
                              const float* __restrict__ Wq,
                              const float* __restrict__ Wv)
{
    int idx = blockIdx.x * blockDim.x + threadIdx.x;   // 3 * 1024 * 128
    if (idx >= 3 * E_ * H_) return;
    int m = idx / (E_ * H_);
    int r = idx % (E_ * H_);
    int k = r / H_;            // coalesced over n
    int n = r % H_;
    const float* W = (m == 0) ? Wq : (m == 1) ? Wk : Wv;
    float w = W[(size_t)k * H_ + n];
    __nv_bfloat16 hi = __float2bfloat16(w);
    float lof = w - __bfloat162float(hi);
    g_Wt_hi[m][n][k] = hi;
    g_Wt_lo[m][n][k] = __float2bfloat16(lof);
}

// ---------------------------------------------------------------------------
// Kernel 1: QKV projection via mma.sync bf16-split GEMM.
// grid = (M/128, 3), 256 threads (8 warps, 2x4).
// Block tile: 128m x 128n x 32k.  Warp tile: 64m x 32n.
// D = Ahi*Bhi + Alo*Bhi + Ahi*Blo  (fp32 accum)
// ---------------------------------------------------------------------------
#define LDA 40      // bf16 row stride, pad 32 -> 40 (conflict-free ldmatrix)
#define BK 32

__global__ __launch_bounds__(256) void qkv_mma_sync(const float* __restrict__ x)
{
    __shared__ __nv_bfloat16 As_hi[128 * LDA];
    __shared__ __nv_bfloat16 As_lo[128 * LDA];
    __shared__ __nv_bfloat16 Ws_hi[128 * LDA];
    __shared__ __nv_bfloat16 Ws_lo[128 * LDA];

    const int tid  = threadIdx.x;
    const int wid  = tid >> 5;
    const int lane = tid & 31;
    const int warp_m = wid >> 2;          // 0..1  (64 rows each)
    const int warp_n = wid & 3;           // 0..3  (32 cols each)
    const int rowBase = blockIdx.x * 128;
    const int mat = blockIdx.y;           // 0:Q 1:K 2:V

    const char* Whi = (const char*)g_Wt_hi + (size_t)mat * H_ * E_ * 2;
    const char* Wlo = (const char*)g_Wt_lo + (size_t)mat * H_ * E_ * 2;
    float* D = (mat == 0) ? g_Q : (mat == 1) ? g_K : g_V;

    const uint32_t sAhi = smem_u32(As_hi);
    const uint32_t sAlo = smem_u32(As_lo);
    const uint32_t sBhi = smem_u32(Ws_hi);
    const uint32_t sBlo = smem_u32(Ws_lo);

    float acc[4][4][4];                   // [m-tile][n-tile][frag]
    #pragma unroll
    for (int i = 0; i < 4; i++)
        #pragma unroll
        for (int j = 0; j < 4; j++)
            #pragma unroll
            for (int f = 0; f < 4; f++) acc[i][j][f] = 0.f;

    // ldmatrix lane address components (computed once)
    const int aq = lane >> 3, ar = lane & 7;          // x4: quad, row
    // A tile (m0,k0): row = m0 + ar + (aq&1)*8, col = k0 + (aq>>1)*8
    // B tile (n0,k0): row = n0 + ar,            col = k0 + (aq&1)*8   (x2)

    for (int k0 = 0; k0 < E_; k0 += BK) {
        __syncthreads();   // previous iteration's consumers done

        // ---- stage A: x fp32 -> bf16 hi/lo ----
        #pragma unroll
        for (int u = 0; u < 4; u++) {
            int i = tid + u * 256;        // 0..1023 float4 slots
            int r = i >> 3, c4 = i & 7;   // 128 rows x 8 float4
            float4 f = *(const float4*)(x + (size_t)(rowBase + r) * E_ + k0 + c4 * 4);
            __nv_bfloat16 h0 = __float2bfloat16(f.x), h1 = __float2bfloat16(f.y);
            __nv_bfloat16 h2 = __float2bfloat16(f.z), h3 = __float2bfloat16(f.w);
            __nv_bfloat16 l0 = __float2bfloat16(f.x - __bfloat162float(h0));
            __nv_bfloat16 l1 = __float2bfloat16(f.y - __bfloat162float(h1));
            __nv_bfloat16 l2 = __float2bfloat16(f.z - __bfloat162float(h2));
            __nv_bfloat16 l3 = __float2bfloat16(f.w - __bfloat162float(h3));
            *(uint2*)(&As_hi[r * LDA + c4 * 4]) = make_uint2(pack_bf2(h0,h1), pack_bf2(h2,h3));
            *(uint2*)(&As_lo[r * LDA + c4 * 4]) = make_uint2(pack_bf2(l0,l1), pack_bf2(l2,l3));
        }
        // ---- stage B: Wt bf16 copy ----
        #pragma unroll
        for (int u = 0; u < 4; u++) {
            int i = tid + u * 256;        // 0..1023 8B slots
            int n = i >> 3, c4 = i & 7;   // 128 n-rows x 8 chunks of 4 bf16
            size_t go = ((size_t)n * E_ + k0 + c4 * 4) * 2;
            *(uint2*)(&Ws_hi[n * LDA + c4 * 4]) = *(const uint2*)(Whi + go);
            *(uint2*)(&Ws_lo[n * LDA + c4 * 4]) = *(const uint2*)(Wlo + go);
        }
        __syncthreads();

        // ---- compute: 2 k-steps x 3 split-products x 16 tiles ----
        #pragma unroll
        for (int ks = 0; ks < 2; ks++) {
            const int kk = ks * 16;
            uint32_t a[4][4], b[4][2];

            // Ahi fragments (4 m-tiles)
            #pragma unroll
            for (int i = 0; i < 4; i++) {
                int row = warp_m * 64 + i * 16 + ar + (aq & 1) * 8;
                int col = kk + (aq >> 1) * 8;
                ldsm_x4(a[i], sAhi + (row * LDA + col) * 2);
            }
            // Bhi fragments (4 n-tiles)
            #pragma unroll
            for (int j = 0; j < 4; j++) {
                int row = warp_n * 32 + j * 8 + ar;
                int col = kk + (aq & 1) * 8;
                ldsm_x2(b[j], sBhi + (row * LDA + col) * 2);
            }
            #pragma unroll
            for (int i = 0; i < 4; i++)
                #pragma unroll
                for (int j = 0; j < 4; j++)
                    mma16816(acc[i][j], a[i], b[j]);          // Ahi*Bhi

            // Blo fragments (reuse Ahi)
            #pragma unroll
            for (int j = 0; j < 4; j++) {
                int row = warp_n * 32 + j * 8 + ar;
                int col = kk + (aq & 1) * 8;
                ldsm_x2(b[j], sBlo + (row * LDA + col) * 2);
            }
            #pragma unroll
            for (int i = 0; i < 4; i++)
                #pragma unroll
                for (int j = 0; j < 4; j++)
                    mma16816(acc[i][j], a[i], b[j]);          // Ahi*Blo

            // Alo fragments, Bhi again
            #pragma unroll
            for (int i = 0; i < 4; i++) {
                int row = warp_m * 64 + i * 16 + ar + (aq & 1) * 8;
                int col = kk + (aq >> 1) * 8;
                ldsm_x4(a[i], sAlo + (row * LDA + col) * 2);
            }
            #pragma unroll
            for (int j = 0; j < 4; j++) {
                int row = warp_n * 32 + j * 8 + ar;
                int col = kk + (aq & 1) * 8;
                ldsm_x2(b[j], sBhi + (row * LDA + col) * 2);
            }
            #pragma unroll
            for (int i = 0; i < 4; i++)
                #pragma unroll
                for (int j = 0; j < 4; j++)
                    mma16816(acc[i][j], a[i], b[j]);          // Alo*Bhi
        }
    }

    // ---- epilogue: fragment -> gmem fp32 ----
    const int gq = lane >> 2, tig = lane & 3;   // c frag: row=m0+gq(+8), col=n0+2*tig(+1)
    #pragma unroll
    for (int i = 0; i < 4; i++) {
        #pragma unroll
        for (int j = 0; j < 4; j++) {
            int row = rowBase + warp_m * 64 + i * 16 + gq;
            int col = warp_n * 32 + j * 8 + 2 * tig;
            *(float2*)(D + (size_t)row * H_ + col) = make_float2(acc[i][j][0], acc[i][j][1]);
            *(float2*)(D + (size_t)(row + 8) * H_ + col) = make_float2(acc[i][j][2], acc[i][j][3]);
        }
    }
}

// ---------------------------------------------------------------------------
// Kernel 2: causal flash attention, fp32 (unchanged, known correct).
// ---------------------------------------------------------------------------
#define QLD 132
#define PLD 68
#define ATTN_SMEM_FLOATS (3*64*QLD + 64*PLD)

__global__ __launch_bounds__(256) void attn_kernel(float* __restrict__ out)
{
    extern __shared__ float sm[];
    float* Qs = sm;
    float* Ks = Qs + 64*QLD;
    float* Vs = Ks + 64*QLD;
    float* Ps = Vs + 64*QLD;

    const int b  = blockIdx.y;
    const int qt = (int)gridDim.x - 1 - (int)blockIdx.x;
    const int q0 = qt * 64;
    const int tid = threadIdx.x;
    const int tq = tid >> 4;
    const int tk = tid & 15;
    const float scale = 0.08838834764831845f;

    #pragma unroll
    for (int u = 0; u < 8; u++) {
        int i = tid + u * 256;
        int r = i >> 5, c4 = i & 31;
        float4 f = *(const float4*)(g_Q + ((size_t)b*T_ + q0 + r) * H_ + c4*4);
        f.x *= scale; f.y *= scale; f.z *= scale; f.w *= scale;
        *(float4*)(&Qs[r*QLD + c4*4]) = f;
    }

    float m_i[4], l_i[4], acc[4][8];
    #pragma unroll
    for (int i = 0; i < 4; i++) {
        m_i[i] = -1e30f; l_i[i] = 0.f;
        #pragma unroll
        for (int j = 0; j < 8; j++) acc[i][j] = 0.f;
    }

    for (int kt = 0; kt <= qt; kt++) {
        __syncthreads();
        const int k0 = kt * 64;
        #pragma unroll
        for (int u = 0; u < 8; u++) {
            int i = tid + u * 256;
            int r = i >> 5, c4 = i & 31;
            size_t g = ((size_t)b*T_ + k0 + r) * H_ + c4*4;
            *(float4*)(&Ks[r*QLD + c4*4]) = *(const float4*)(g_K + g);
            *(float4*)(&Vs[r*QLD + c4*4]) = *(const float4*)(g_V + g);
        }
        __syncthreads();

        float s[4][4];
        #pragma unroll
        for (int i = 0; i < 4; i++)
            #pragma unroll
            for (int j = 0; j < 4; j++) s[i][j] = 0.f;

        #pragma unroll 4
        for (int h4 = 0; h4 < 32; h4++) {
            float4 q[4], kk[4];
            #pragma unroll
            for (int i = 0; i < 4; i++)
                q[i] = *(const float4*)(&Qs[(tq*4+i)*QLD + h4*4]);
            #pragma unroll
            for (int j = 0; j < 4; j++)
                kk[j] = *(const float4*)(&Ks[(tk*4+j)*QLD + h4*4]);
            #pragma unroll
            for (int i = 0; i < 4; i++)
                #pragma unroll
                for (int j = 0; j < 4; j++)
                    s[i][j] += q[i].x*kk[j].x + q[i].y*kk[j].y
                             + q[i].z*kk[j].z + q[i].w*kk[j].w;
        }

        if (kt == qt) {
            #pragma unroll
            for (int i = 0; i < 4; i++)
                #pragma unroll
                for (int j = 0; j < 4; j++)
                    if (tk*4 + j > tq*4 + i) s[i][j] = -1e30f;
        }

        #pragma unroll
        for (int i = 0; i < 4; i++) {
            float rmax = fmaxf(fmaxf(s[i][0], s[i][1]), fmaxf(s[i][2], s[i][3]));
            #pragma unroll
            for (int o = 8; o >= 1; o >>= 1)
                rmax = fmaxf(rmax, __shfl_xor_sync(0xffffffffu, rmax, o));
            float mnew  = fmaxf(m_i[i], rmax);
            float alpha = __expf(m_i[i] - mnew);
            float rsum = 0.f;
            #pragma unroll
            for (int j = 0; j < 4; j++) { s[i][j] = __expf(s[i][j] - mnew); rsum += s[i][j]; }
            #pragma unroll
            for (int o = 8; o >= 1; o >>= 1)
                rsum += __shfl_xor_sync(0xffffffffu, rsum, o);
            l_i[i] = l_i[i] * alpha + rsum;
            m_i[i] = mnew;
            *(float4*)(&Ps[(tq*4+i)*PLD + tk*4]) =
                make_float4(s[i][0], s[i][1], s[i][2], s[i][3]);
            #pragma unroll
            for (int j = 0; j < 8; j++) acc[i][j] *= alpha;
        }
        __syncthreads();

        #pragma unroll 4
        for (int j = 0; j < 64; j++) {
            float4 v0 = *(const float4*)(&Vs[j*QLD + tk*8]);
            float4 v1 = *(const float4*)(&Vs[j*QLD + tk*8 + 4]);
            #pragma unroll
            for (int i = 0; i < 4; i++) {
                float p = Ps[(tq*4+i)*PLD + j];
                acc[i][0] += p*v0.x; acc[i][1] += p*v0.y;
                acc[i][2] += p*v0.z; acc[i][3] += p*v0.w;
                acc[i][4] += p*v1.x; acc[i][5] += p*v1.y;
                acc[i][6] += p*v1.z; acc[i][7] += p*v1.w;
            }
        }
    }

    #pragma unroll
    for (int i = 0; i < 4; i++) {
        float inv = 1.f / l_i[i];
        size_t row = (size_t)b*T_ + q0 + tq*4 + i;
        float4 o0 = make_float4(acc[i][0]*inv, acc[i][1]*inv, acc[i][2]*inv, acc[i][3]*inv);
        float4 o1 = make_float4(acc[i][4]*inv, acc[i][5]*inv, acc[i][6]*inv, acc[i][7]*inv);
        *(float4*)(out + row * H_ + tk*8)     = o0;
        *(float4*)(out + row * H_ + tk*8 + 4) = o1;
    }
}

// ---------------------------------------------------------------------------
extern "C" void kernel_launch(void* const* d_in, const int* in_sizes, int n_in,
                              void* d_out, int out_size)
{
    const float* x  = (const float*)d_in[0];
    const float* Wk = (const float*)d_in[1];
    const float* Wq = (const float*)d_in[2];
    const float* Wv = (const float*)d_in[3];
    float* out = (float*)d_out;

    wsplit_kernel<<<(3 * E_ * H_ + 255) / 256, 256>>>(Wk, Wq, Wv);

    dim3 g1(M_ / 128, 3);
    qkv_mma_sync<<<g1, 256>>>(x);

    size_t smem = (size_t)ATTN_SMEM_FLOATS * sizeof(float);
    cudaFuncSetAttribute(attn_kernel, cudaFuncAttributeMaxDynamicSharedMemorySize, (int)smem);
    dim3 g2(T_ / 64, B_);
    attn_kernel<<<g2, 256, smem>>>(out);
}

// round 7
// speedup vs baseline: 2.9737x; 2.7753x over previous
#include <cuda_runtime.h>
#include <cuda_bf16.h>
#include <cuda_fp16.h>
#include <cstdint>

#define B_ 16
#define T_ 2048
#define E_ 1024
#define H_ 128
#define M_ (B_*T_)

// ---------------------------------------------------------------------------
// Device scratch
// ---------------------------------------------------------------------------
__device__ __align__(16) __half g_Qh[(size_t)M_ * H_];   // pre-scaled by H^-0.5
__device__ __align__(16) __half g_Kh[(size_t)M_ * H_];
__device__ __align__(16) __half g_Vh[(size_t)M_ * H_];
// Transposed bf16-split weights: [matrix(Q,K,V)][n=128][k=1024]
__device__ __align__(16) __nv_bfloat16 g_Wt_hi[3][H_][E_];
__device__ __align__(16) __nv_bfloat16 g_Wt_lo[3][H_][E_];

// ---------------------------------------------------------------------------
// Baseline-PTX tensor-core helpers (ldmatrix + mma.sync, sm_80+ ISA)
// ---------------------------------------------------------------------------
__device__ __forceinline__ uint32_t smem_u32(const void* p) {
    uint32_t a;
    asm("{ .reg .u64 t; cvta.to.shared.u64 t, %1; cvt.u32.u64 %0, t; }" : "=r"(a) : "l"(p));
    return a;
}
__device__ __forceinline__ void ldsm_x4(uint32_t* r, uint32_t addr) {
    asm volatile("ldmatrix.sync.aligned.m8n8.x4.shared.b16 {%0,%1,%2,%3}, [%4];"
                 : "=r"(r[0]), "=r"(r[1]), "=r"(r[2]), "=r"(r[3]) : "r"(addr));
}
__device__ __forceinline__ void ldsm_x4t(uint32_t* r, uint32_t addr) {
    asm volatile("ldmatrix.sync.aligned.m8n8.x4.trans.shared.b16 {%0,%1,%2,%3}, [%4];"
                 : "=r"(r[0]), "=r"(r[1]), "=r"(r[2]), "=r"(r[3]) : "r"(addr));
}
__device__ __forceinline__ void ldsm_x2(uint32_t* r, uint32_t addr) {
    asm volatile("ldmatrix.sync.aligned.m8n8.x2.shared.b16 {%0,%1}, [%2];"
                 : "=r"(r[0]), "=r"(r[1]) : "r"(addr));
}
__device__ __forceinline__ void mma_bf(float* d, const uint32_t* a, const uint32_t* b) {
    asm volatile(
        "mma.sync.aligned.m16n8k16.row.col.f32.bf16.bf16.f32 "
        "{%0,%1,%2,%3}, {%4,%5,%6,%7}, {%8,%9}, {%0,%1,%2,%3};"
        : "+f"(d[0]), "+f"(d[1]), "+f"(d[2]), "+f"(d[3])
        : "r"(a[0]), "r"(a[1]), "r"(a[2]), "r"(a[3]), "r"(b[0]), "r"(b[1]));
}
__device__ __forceinline__ void mma_fp16(float* d, const uint32_t* a, const uint32_t* b) {
    asm volatile(
        "mma.sync.aligned.m16n8k16.row.col.f32.f16.f16.f32 "
        "{%0,%1,%2,%3}, {%4,%5,%6,%7}, {%8,%9}, {%0,%1,%2,%3};"
        : "+f"(d[0]), "+f"(d[1]), "+f"(d[2]), "+f"(d[3])
        : "r"(a[0]), "r"(a[1]), "r"(a[2]), "r"(a[3]), "r"(b[0]), "r"(b[1]));
}
__device__ __forceinline__ uint32_t pack_bf2(__nv_bfloat16 a, __nv_bfloat16 b) {
    __nv_bfloat162 t = __halves2bfloat162(a, b);
    return *reinterpret_cast<uint32_t*>(&t);
}
__device__ __forceinline__ uint32_t pack_h2(float a, float b) {
    __half2 t = __floats2half2_rn(a, b);
    return *reinterpret_cast<uint32_t*>(&t);
}

// ---------------------------------------------------------------------------
// Kernel 0: weight transpose + bf16 hi/lo split
// ---------------------------------------------------------------------------
__global__ void wsplit_kernel(const float* __restrict__ Wk,
                              const float* __restrict__ Wq,
                              const float* __restrict__ Wv)
{
    int idx = blockIdx.x * blockDim.x + threadIdx.x;
    if (idx >= 3 * E_ * H_) return;
    int m = idx / (E_ * H_);
    int r = idx % (E_ * H_);
    int k = r / H_;
    int n = r % H_;
    const float* W = (m == 0) ? Wq : (m == 1) ? Wk : Wv;
    float w = W[(size_t)k * H_ + n];
    __nv_bfloat16 hi = __float2bfloat16(w);
    float lof = w - __bfloat162float(hi);
    g_Wt_hi[m][n][k] = hi;
    g_Wt_lo[m][n][k] = __float2bfloat16(lof);
}

// ---------------------------------------------------------------------------
// Kernel 1: QKV projection (bf16-split mma.sync), outputs fp16 Q/K/V.
// Q is pre-scaled by H^-0.5.
// ---------------------------------------------------------------------------
#define LDA 40
#define BK 32

__global__ __launch_bounds__(256) void qkv_mma_sync(const float* __restrict__ x)
{
    __shared__ __nv_bfloat16 As_hi[128 * LDA];
    __shared__ __nv_bfloat16 As_lo[128 * LDA];
    __shared__ __nv_bfloat16 Ws_hi[128 * LDA];
    __shared__ __nv_bfloat16 Ws_lo[128 * LDA];

    const int tid  = threadIdx.x;
    const int wid  = tid >> 5;
    const int lane = tid & 31;
    const int warp_m = wid >> 2;
    const int warp_n = wid & 3;
    const int rowBase = blockIdx.x * 128;
    const int mat = blockIdx.y;

    const char* Whi = (const char*)g_Wt_hi + (size_t)mat * H_ * E_ * 2;
    const char* Wlo = (const char*)g_Wt_lo + (size_t)mat * H_ * E_ * 2;
    __half* D = (mat == 0) ? g_Qh : (mat == 1) ? g_Kh : g_Vh;
    const float mul = (mat == 0) ? 0.08838834764831845f : 1.0f;

    const uint32_t sAhi = smem_u32(As_hi);
    const uint32_t sAlo = smem_u32(As_lo);
    const uint32_t sBhi = smem_u32(Ws_hi);
    const uint32_t sBlo = smem_u32(Ws_lo);

    float acc[4][4][4];
    #pragma unroll
    for (int i = 0; i < 4; i++)
        #pragma unroll
        for (int j = 0; j < 4; j++)
            #pragma unroll
            for (int f = 0; f < 4; f++) acc[i][j][f] = 0.f;

    const int aq = lane >> 3, ar = lane & 7;

    for (int k0 = 0; k0 < E_; k0 += BK) {
        __syncthreads();
        #pragma unroll
        for (int u = 0; u < 4; u++) {
            int i = tid + u * 256;
            int r = i >> 3, c4 = i & 7;
            float4 f = *(const float4*)(x + (size_t)(rowBase + r) * E_ + k0 + c4 * 4);
            __nv_bfloat16 h0 = __float2bfloat16(f.x), h1 = __float2bfloat16(f.y);
            __nv_bfloat16 h2 = __float2bfloat16(f.z), h3 = __float2bfloat16(f.w);
            __nv_bfloat16 l0 = __float2bfloat16(f.x - __bfloat162float(h0));
            __nv_bfloat16 l1 = __float2bfloat16(f.y - __bfloat162float(h1));
            __nv_bfloat16 l2 = __float2bfloat16(f.z - __bfloat162float(h2));
            __nv_bfloat16 l3 = __float2bfloat16(f.w - __bfloat162float(h3));
            *(uint2*)(&As_hi[r * LDA + c4 * 4]) = make_uint2(pack_bf2(h0,h1), pack_bf2(h2,h3));
            *(uint2*)(&As_lo[r * LDA + c4 * 4]) = make_uint2(pack_bf2(l0,l1), pack_bf2(l2,l3));
        }
        #pragma unroll
        for (int u = 0; u < 4; u++) {
            int i = tid + u * 256;
            int n = i >> 3, c4 = i & 7;
            size_t go = ((size_t)n * E_ + k0 + c4 * 4) * 2;
            *(uint2*)(&Ws_hi[n * LDA + c4 * 4]) = *(const uint2*)(Whi + go);
            *(uint2*)(&Ws_lo[n * LDA + c4 * 4]) = *(const uint2*)(Wlo + go);
        }
        __syncthreads();

        #pragma unroll
        for (int ks = 0; ks < 2; ks++) {
            const int kk = ks * 16;
            uint32_t a[4][4], b[4][2];
            #pragma unroll
            for (int i = 0; i < 4; i++) {
                int row = warp_m * 64 + i * 16 + ar + (aq & 1) * 8;
                int col = kk + (aq >> 1) * 8;
                ldsm_x4(a[i], sAhi + (row * LDA + col) * 2);
            }
            #pragma unroll
            for (int j = 0; j < 4; j++) {
                int row = warp_n * 32 + j * 8 + ar;
                int col = kk + (aq & 1) * 8;
                ldsm_x2(b[j], sBhi + (row * LDA + col) * 2);
            }
            #pragma unroll
            for (int i = 0; i < 4; i++)
                #pragma unroll
                for (int j = 0; j < 4; j++)
                    mma_bf(acc[i][j], a[i], b[j]);            // Ahi*Bhi
            #pragma unroll
            for (int j = 0; j < 4; j++) {
                int row = warp_n * 32 + j * 8 + ar;
                int col = kk + (aq & 1) * 8;
                ldsm_x2(b[j], sBlo + (row * LDA + col) * 2);
            }
            #pragma unroll
            for (int i = 0; i < 4; i++)
                #pragma unroll
                for (int j = 0; j < 4; j++)
                    mma_bf(acc[i][j], a[i], b[j]);            // Ahi*Blo
            #pragma unroll
            for (int i = 0; i < 4; i++) {
                int row = warp_m * 64 + i * 16 + ar + (aq & 1) * 8;
                int col = kk + (aq >> 1) * 8;
                ldsm_x4(a[i], sAlo + (row * LDA + col) * 2);
            }
            #pragma unroll
            for (int j = 0; j < 4; j++) {
                int row = warp_n * 32 + j * 8 + ar;
                int col = kk + (aq & 1) * 8;
                ldsm_x2(b[j], sBhi + (row * LDA + col) * 2);
            }
            #pragma unroll
            for (int i = 0; i < 4; i++)
                #pragma unroll
                for (int j = 0; j < 4; j++)
                    mma_bf(acc[i][j], a[i], b[j]);            // Alo*Bhi
        }
    }

    const int gq = lane >> 2, tig = lane & 3;
    #pragma unroll
    for (int i = 0; i < 4; i++) {
        #pragma unroll
        for (int j = 0; j < 4; j++) {
            int row = rowBase + warp_m * 64 + i * 16 + gq;
            int col = warp_n * 32 + j * 8 + 2 * tig;
            __half2 h0 = __floats2half2_rn(acc[i][j][0] * mul, acc[i][j][1] * mul);
            __half2 h1 = __floats2half2_rn(acc[i][j][2] * mul, acc[i][j][3] * mul);
            *(__half2*)(D + (size_t)row * H_ + col) = h0;
            *(__half2*)(D + (size_t)(row + 8) * H_ + col) = h1;
        }
    }
}

// ---------------------------------------------------------------------------
// Kernel 2: causal flash attention with fp16 mma.sync (FA2 layout).
// BQ=64, BK=64, 4 warps; each warp owns 16 q-rows x full 128 h.
// grid = (T/64=32, B); qt descending for load balance.
// ---------------------------------------------------------------------------
#define LDH 136

__global__ __launch_bounds__(128) void attn_mma(float* __restrict__ out)
{
    extern __shared__ __half smh[];
    __half* Qs = smh;                 // 64 x LDH
    __half* Ks = smh + 64 * LDH;
    __half* Vs = smh + 128 * LDH;

    const int b  = blockIdx.y;
    const int qt = (int)gridDim.x - 1 - (int)blockIdx.x;
    const int q0 = qt * 64;
    const int tid = threadIdx.x;
    const int wid = tid >> 5;
    const int lane = tid & 31;
    const int ar = lane & 7, aq = lane >> 3;
    const int gq = lane >> 2, tig = lane & 3;
    const int tr = lane & 15, tc = (lane >> 4) * 8;   // for ldmatrix.trans on V

    const uint32_t sQ = smem_u32(Qs);
    const uint32_t sK = smem_u32(Ks);
    const uint32_t sV = smem_u32(Vs);

    // stage Q (fp16, pre-scaled at projection time)
    #pragma unroll
    for (int u = 0; u < 8; u++) {
        int i = tid + u * 128;          // 1024 uint4 slots: 64 rows x 16 chunks
        int r = i >> 4, c8 = i & 15;
        *(uint4*)(&Qs[r * LDH + c8 * 8]) =
            *(const uint4*)(g_Qh + ((size_t)b * T_ + q0 + r) * H_ + c8 * 8);
    }

    float m0 = -1e30f, m1 = -1e30f, l0 = 0.f, l1 = 0.f;
    float acc[16][4];
    #pragma unroll
    for (int t = 0; t < 16; t++)
        #pragma unroll
        for (int f = 0; f < 4; f++) acc[t][f] = 0.f;

    for (int kt = 0; kt <= qt; kt++) {
        __syncthreads();
        const int k0 = kt * 64;
        #pragma unroll
        for (int u = 0; u < 8; u++) {
            int i = tid + u * 128;
            int r = i >> 4, c8 = i & 15;
            size_t g = ((size_t)b * T_ + k0 + r) * H_ + c8 * 8;
            *(uint4*)(&Ks[r * LDH + c8 * 8]) = *(const uint4*)(g_Kh + g);
            *(uint4*)(&Vs[r * LDH + c8 * 8]) = *(const uint4*)(g_Vh + g);
        }
        __syncthreads();

        // ---- S = Q K^T : per warp 16x64, 8 k-steps of 16 over h ----
        float sc[8][4];
        #pragma unroll
        for (int j = 0; j < 8; j++)
            #pragma unroll
            for (int f = 0; f < 4; f++) sc[j][f] = 0.f;

        #pragma unroll
        for (int s = 0; s < 8; s++) {
            uint32_t a[4];
            ldsm_x4(a, sQ + ((wid * 16 + ar + (aq & 1) * 8) * LDH
                             + s * 16 + (aq >> 1) * 8) * 2);
            #pragma unroll
            for (int j = 0; j < 8; j++) {
                uint32_t bb[2];
                ldsm_x2(bb, sK + ((j * 8 + ar) * LDH + s * 16 + (aq & 1) * 8) * 2);
                mma_fp16(sc[j], a, bb);
            }
        }

        // ---- diagonal tile causal mask ----
        if (kt == qt) {
            const int lr0 = wid * 16 + gq, lr1 = lr0 + 8;
            #pragma unroll
            for (int j = 0; j < 8; j++) {
                int c = j * 8 + 2 * tig;
                if (c     > lr0) sc[j][0] = -1e30f;
                if (c + 1 > lr0) sc[j][1] = -1e30f;
                if (c     > lr1) sc[j][2] = -1e30f;
                if (c + 1 > lr1) sc[j][3] = -1e30f;
            }
        }

        // ---- online softmax ----
        float mt0 = -1e30f, mt1 = -1e30f;
        #pragma unroll
        for (int j = 0; j < 8; j++) {
            mt0 = fmaxf(mt0, fmaxf(sc[j][0], sc[j][1]));
            mt1 = fmaxf(mt1, fmaxf(sc[j][2], sc[j][3]));
        }
        mt0 = fmaxf(mt0, __shfl_xor_sync(0xffffffffu, mt0, 1));
        mt0 = fmaxf(mt0, __shfl_xor_sync(0xffffffffu, mt0, 2));
        mt1 = fmaxf(mt1, __shfl_xor_sync(0xffffffffu, mt1, 1));
        mt1 = fmaxf(mt1, __shfl_xor_sync(0xffffffffu, mt1, 2));

        float mn0 = fmaxf(m0, mt0), mn1 = fmaxf(m1, mt1);
        float al0 = __expf(m0 - mn0), al1 = __expf(m1 - mn1);
        m0 = mn0; m1 = mn1;

        uint32_t pp[8][2];
        float rs0 = 0.f, rs1 = 0.f;
        #pragma unroll
        for (int j = 0; j < 8; j++) {
            float e0 = __expf(sc[j][0] - mn0);
            float e1 = __expf(sc[j][1] - mn0);
            float e2 = __expf(sc[j][2] - mn1);
            float e3 = __expf(sc[j][3] - mn1);
            rs0 += e0 + e1; rs1 += e2 + e3;
            pp[j][0] = pack_h2(e0, e1);
            pp[j][1] = pack_h2(e2, e3);
        }
        rs0 += __shfl_xor_sync(0xffffffffu, rs0, 1);
        rs0 += __shfl_xor_sync(0xffffffffu, rs0, 2);
        rs1 += __shfl_xor_sync(0xffffffffu, rs1, 1);
        rs1 += __shfl_xor_sync(0xffffffffu, rs1, 2);
        l0 = l0 * al0 + rs0;
        l1 = l1 * al1 + rs1;

        #pragma unroll
        for (int t = 0; t < 16; t++) {
            acc[t][0] *= al0; acc[t][1] *= al0;
            acc[t][2] *= al1; acc[t][3] *= al1;
        }

        // ---- O += P V : 4 k-steps of 16 tokens, 8 h-tile pairs ----
        #pragma unroll
        for (int s = 0; s < 4; s++) {
            uint32_t a[4] = { pp[2*s][0], pp[2*s][1], pp[2*s+1][0], pp[2*s+1][1] };
            #pragma unroll
            for (int j2 = 0; j2 < 8; j2++) {
                uint32_t bb[4];
                ldsm_x4t(bb, sV + ((s * 16 + tr) * LDH + j2 * 16 + tc) * 2);
                mma_fp16(acc[2*j2],     a, bb);
                mma_fp16(acc[2*j2 + 1], a, bb + 2);
            }
        }
    }

    // ---- epilogue ----
    const float inv0 = 1.f / l0, inv1 = 1.f / l1;
    #pragma unroll
    for (int t = 0; t < 16; t++) {
        int row = q0 + wid * 16 + gq;
        int col = t * 8 + 2 * tig;
        *(float2*)(out + ((size_t)b * T_ + row) * H_ + col) =
            make_float2(acc[t][0] * inv0, acc[t][1] * inv0);
        *(float2*)(out + ((size_t)b * T_ + row + 8) * H_ + col) =
            make_float2(acc[t][2] * inv1, acc[t][3] * inv1);
    }
}

// ---------------------------------------------------------------------------
extern "C" void kernel_launch(void* const* d_in, const int* in_sizes, int n_in,
                              void* d_out, int out_size)
{
    const float* x  = (const float*)d_in[0];
    const float* Wk = (const float*)d_in[1];
    const float* Wq = (const float*)d_in[2];
    const float* Wv = (const float*)d_in[3];
    float* out = (float*)d_out;

    wsplit_kernel<<<(3 * E_ * H_ + 255) / 256, 256>>>(Wk, Wq, Wv);

    dim3 g1(M_ / 128, 3);
    qkv_mma_sync<<<g1, 256>>>(x);

    const int attn_smem = 192 * LDH * 2;
    cudaFuncSetAttribute(attn_mma, cudaFuncAttributeMaxDynamicSharedMemorySize, attn_smem);
    dim3 g2(T_ / 64, B_);
    attn_mma<<<g2, 128, attn_smem>>>(out);
}

// round 8
// speedup vs baseline: 5.8048x; 1.9520x over previous
#include <cuda_runtime.h>
#include <cuda_fp16.h>
#include <cstdint>

#define B_ 16
#define T_ 2048
#define E_ 1024
#define H_ 128
#define M_ (B_*T_)

// ---------------------------------------------------------------------------
// Device scratch
// ---------------------------------------------------------------------------
__device__ __align__(16) __half g_xh[(size_t)M_ * E_];   // x rounded to fp16
__device__ __align__(16) __half g_Qh[(size_t)M_ * H_];   // pre-scaled by H^-0.5
__device__ __align__(16) __half g_Kh[(size_t)M_ * H_];
__device__ __align__(16) __half g_Vh[(size_t)M_ * H_];
// Transposed fp16-split weights: [matrix(Q,K,V)][n=128][k=1024]; Wq pre-scaled
__device__ __align__(16) __half g_Wt_hi[3][H_][E_];
__device__ __align__(16) __half g_Wt_lo[3][H_][E_];

// ---------------------------------------------------------------------------
// Baseline-PTX helpers (ldmatrix + mma.sync + cp.async, sm_80+ ISA)
// ---------------------------------------------------------------------------
__device__ __forceinline__ uint32_t smem_u32(const void* p) {
    uint32_t a;
    asm("{ .reg .u64 t; cvta.to.shared.u64 t, %1; cvt.u32.u64 %0, t; }" : "=r"(a) : "l"(p));
    return a;
}
__device__ __forceinline__ void ldsm_x4(uint32_t* r, uint32_t addr) {
    asm volatile("ldmatrix.sync.aligned.m8n8.x4.shared.b16 {%0,%1,%2,%3}, [%4];"
                 : "=r"(r[0]), "=r"(r[1]), "=r"(r[2]), "=r"(r[3]) : "r"(addr));
}
__device__ __forceinline__ void ldsm_x4t(uint32_t* r, uint32_t addr) {
    asm volatile("ldmatrix.sync.aligned.m8n8.x4.trans.shared.b16 {%0,%1,%2,%3}, [%4];"
                 : "=r"(r[0]), "=r"(r[1]), "=r"(r[2]), "=r"(r[3]) : "r"(addr));
}
__device__ __forceinline__ void mma_fp16(float* d, const uint32_t* a, const uint32_t* b) {
    asm volatile(
        "mma.sync.aligned.m16n8k16.row.col.f32.f16.f16.f32 "
        "{%0,%1,%2,%3}, {%4,%5,%6,%7}, {%8,%9}, {%0,%1,%2,%3};"
        : "+f"(d[0]), "+f"(d[1]), "+f"(d[2]), "+f"(d[3])
        : "r"(a[0]), "r"(a[1]), "r"(a[2]), "r"(a[3]), "r"(b[0]), "r"(b[1]));
}
__device__ __forceinline__ uint32_t pack_h2(float a, float b) {
    __half2 t = __floats2half2_rn(a, b);
    return *reinterpret_cast<uint32_t*>(&t);
}
#define CP_ASYNC16(saddr, gptr) \
    asm volatile("cp.async.cg.shared.global [%0], [%1], 16;" :: "r"(saddr), "l"(gptr))
#define CP_COMMIT() asm volatile("cp.async.commit_group;" ::: "memory")
#define CP_WAIT1()  asm volatile("cp.async.wait_group 1;" ::: "memory")

// ---------------------------------------------------------------------------
// Kernel A: x fp32 -> fp16
// ---------------------------------------------------------------------------
__global__ __launch_bounds__(256) void xhalf_kernel(const float* __restrict__ x)
{
    size_t i = (size_t)blockIdx.x * 256 + threadIdx.x;   // over float4s
    float4 f = ((const float4*)x)[i];
    ((uint2*)g_xh)[i] = make_uint2(pack_h2(f.x, f.y), pack_h2(f.z, f.w));
}

// ---------------------------------------------------------------------------
// Kernel B: weight transpose + fp16 hi/lo split; Wq scaled by H^-0.5
// ---------------------------------------------------------------------------
__global__ void wsplit_kernel(const float* __restrict__ Wk,
                              const float* __restrict__ Wq,
                              const float* __restrict__ Wv)
{
    int idx = blockIdx.x * blockDim.x + threadIdx.x;
    if (idx >= 3 * E_ * H_) return;
    int m = idx / (E_ * H_);
    int r = idx % (E_ * H_);
    int k = r / H_;
    int n = r % H_;
    const float* W = (m == 0) ? Wq : (m == 1) ? Wk : Wv;
    float w = W[(size_t)k * H_ + n];
    if (m == 0) w *= 0.08838834764831845f;      // fold H^-0.5 into Wq
    __half hi = __float2half_rn(w);
    float lof = w - __half2float(hi);
    g_Wt_hi[m][n][k] = hi;
    g_Wt_lo[m][n][k] = __float2half_rn(lof);
}

// ---------------------------------------------------------------------------
// Kernel 1: QKV projection.  D = xh @ (Whi + Wlo), fp32 accum, fp16 out.
// grid (M/128, 3), 256 threads (8 warps, 2x4). Block tile 128x128x32.
// cp.async double-buffered stages: [A | Whi | Wlo] per stage.
// ---------------------------------------------------------------------------
#define LDA 40
#define QTILE (128 * LDA)          // halves per tile
#define QSTG  (3 * QTILE)          // halves per stage

__global__ __launch_bounds__(256) void qkv_mma_sync()
{
    extern __shared__ __half qsm[];
    const uint32_t sBase = smem_u32(qsm);

    const int tid  = threadIdx.x;
    const int wid  = tid >> 5;
    const int lane = tid & 31;
    const int warp_m = wid >> 2;
    const int warp_n = wid & 3;
    const int rowBase = blockIdx.x * 128;
    const int mat = blockIdx.y;

    const __half* Whi = &g_Wt_hi[mat][0][0];
    const __half* Wlo = &g_Wt_lo[mat][0][0];
    __half* D = (mat == 0) ? g_Qh : (mat == 1) ? g_Kh : g_Vh;

    const int aq = lane >> 3, ar = lane & 7;
    const int ldr = tid >> 2, ldc = (tid & 3) * 8;   // cp.async: 128 rows x 4 chunks

    // issue loads for chunk k0 into stage s (2 rows per thread per tile)
    auto issue = [&](int k0, int s) {
        uint32_t base = sBase + s * QSTG * 2;
        #pragma unroll
        for (int u = 0; u < 2; u++) {
            int r = ldr + u * 64;
            uint32_t so = (uint32_t)(r * LDA + ldc) * 2;
            CP_ASYNC16(base + so,
                       g_xh + (size_t)(rowBase + r) * E_ + k0 + ldc);
            CP_ASYNC16(base + QTILE * 2 + so, Whi + (size_t)r * E_ + k0 + ldc);
            CP_ASYNC16(base + 2 * QTILE * 2 + so, Wlo + (size_t)r * E_ + k0 + ldc);
        }
    };

    float acc[4][4][4];
    #pragma unroll
    for (int i = 0; i < 4; i++)
        #pragma unroll
        for (int j = 0; j < 4; j++)
            #pragma unroll
            for (int f = 0; f < 4; f++) acc[i][j][f] = 0.f;

    issue(0, 0);
    CP_COMMIT();

    for (int c = 0; c < 32; c++) {
        __syncthreads();                       // stage (c+1)&1 free everywhere
        if (c < 31) issue((c + 1) * 32, (c + 1) & 1);
        CP_COMMIT();
        CP_WAIT1();                            // chunk c resident
        __syncthreads();

        const uint32_t sA  = sBase + (c & 1) * QSTG * 2;
        const uint32_t sBh = sA + QTILE * 2;
        const uint32_t sBl = sBh + QTILE * 2;

        #pragma unroll
        for (int ks = 0; ks < 2; ks++) {
            const int kk = ks * 16;
            uint32_t a[4][4];
            #pragma unroll
            for (int i = 0; i < 4; i++)
                ldsm_x4(a[i], sA + ((warp_m * 64 + i * 16 + ar + (aq & 1) * 8) * LDA
                                    + kk + (aq >> 1) * 8) * 2);
            uint32_t b[4][2];
            #pragma unroll
            for (int jp = 0; jp < 2; jp++) {
                uint32_t bb[4];
                ldsm_x4(bb, sBh + ((warp_n * 32 + jp * 16 + (aq >> 1) * 8 + ar) * LDA
                                   + kk + (aq & 1) * 8) * 2);
                b[2*jp][0] = bb[0]; b[2*jp][1] = bb[1];
                b[2*jp+1][0] = bb[2]; b[2*jp+1][1] = bb[3];
            }
            #pragma unroll
            for (int i = 0; i < 4; i++)
                #pragma unroll
                for (int j = 0; j < 4; j++)
                    mma_fp16(acc[i][j], a[i], b[j]);            // A*Whi
            #pragma unroll
            for (int jp = 0; jp < 2; jp++) {
                uint32_t bb[4];
                ldsm_x4(bb, sBl + ((warp_n * 32 + jp * 16 + (aq >> 1) * 8 + ar) * LDA
                                   + kk + (aq & 1) * 8) * 2);
                b[2*jp][0] = bb[0]; b[2*jp][1] = bb[1];
                b[2*jp+1][0] = bb[2]; b[2*jp+1][1] = bb[3];
            }
            #pragma unroll
            for (int i = 0; i < 4; i++)
                #pragma unroll
                for (int j = 0; j < 4; j++)
                    mma_fp16(acc[i][j], a[i], b[j]);            // A*Wlo
        }
    }

    const int gq = lane >> 2, tig = lane & 3;
    #pragma unroll
    for (int i = 0; i < 4; i++) {
        #pragma unroll
        for (int j = 0; j < 4; j++) {
            int row = rowBase + warp_m * 64 + i * 16 + gq;
            int col = warp_n * 32 + j * 8 + 2 * tig;
            *(__half2*)(D + (size_t)row * H_ + col) =
                __floats2half2_rn(acc[i][j][0], acc[i][j][1]);
            *(__half2*)(D + (size_t)(row + 8) * H_ + col) =
                __floats2half2_rn(acc[i][j][2], acc[i][j][3]);
        }
    }
}

// ---------------------------------------------------------------------------
// Kernel 2: causal flash attention, fp16 mma.sync, cp.async double-buffered.
// BQ=64, BK=64, 4 warps; each warp owns 16 q-rows x full 128 h.
// smem: Q | K[2] | V[2], LDH=136.
// ---------------------------------------------------------------------------
#define LDH 136
#define ATT_SMEM (320 * LDH * 2)   // bytes

__global__ __launch_bounds__(128) void attn_mma(float* __restrict__ out)
{
    extern __shared__ __half smh[];
    __half* Qs = smh;
    const uint32_t sQ  = smem_u32(Qs);
    const uint32_t sK0 = sQ + 64 * LDH * 2;    // stage stride 64*LDH*2
    const uint32_t sV0 = sQ + 192 * LDH * 2;

    const int b  = blockIdx.y;
    const int qt = (int)gridDim.x - 1 - (int)blockIdx.x;
    const int q0 = qt * 64;
    const int tid = threadIdx.x;
    const int wid = tid >> 5;
    const int lane = tid & 31;
    const int ar = lane & 7, aq = lane >> 3;
    const int gq = lane >> 2, tig = lane & 3;
    const int tr = lane & 15, tc = (lane >> 4) * 8;
    const int ldr = tid >> 4, ldc = (tid & 15) * 8;   // 64 rows x 16 chunks, 8/thread

    // stage Q
    #pragma unroll
    for (int u = 0; u < 8; u++) {
        int i = tid + u * 128;
        int r = i >> 4, c8 = i & 15;
        *(uint4*)(&Qs[r * LDH + c8 * 8]) =
            *(const uint4*)(g_Qh + ((size_t)b * T_ + q0 + r) * H_ + c8 * 8);
    }

    auto issue = [&](int kt, int s) {
        const int k0 = kt * 64;
        uint32_t kb = sK0 + s * 64 * LDH * 2;
        uint32_t vb = sV0 + s * 64 * LDH * 2;
        #pragma unroll
        for (int u = 0; u < 8; u++) {
            int r = ldr + u * 8;
            size_t g = ((size_t)b * T_ + k0 + r) * H_ + ldc;
            uint32_t so = (uint32_t)(r * LDH + ldc) * 2;
            CP_ASYNC16(kb + so, g_Kh + g);
            CP_ASYNC16(vb + so, g_Vh + g);
        }
    };

    float m0 = -1e30f, m1 = -1e30f, l0 = 0.f, l1 = 0.f;
    float acc[16][4];
    #pragma unroll
    for (int t = 0; t < 16; t++)
        #pragma unroll
        for (int f = 0; f < 4; f++) acc[t][f] = 0.f;

    issue(0, 0);
    CP_COMMIT();

    for (int kt = 0; kt <= qt; kt++) {
        __syncthreads();                      // stage (kt+1)&1 free everywhere
        if (kt < qt) issue(kt + 1, (kt + 1) & 1);
        CP_COMMIT();
        CP_WAIT1();                           // tile kt resident
        __syncthreads();

        const uint32_t sK = sK0 + (kt & 1) * 64 * LDH * 2;
        const uint32_t sV = sV0 + (kt & 1) * 64 * LDH * 2;

        // ---- S = Q K^T ----
        float sc[8][4];
        #pragma unroll
        for (int j = 0; j < 8; j++)
            #pragma unroll
            for (int f = 0; f < 4; f++) sc[j][f] = 0.f;

        #pragma unroll
        for (int s = 0; s < 8; s++) {
            uint32_t a[4];
            ldsm_x4(a, sQ + ((wid * 16 + ar + (aq & 1) * 8) * LDH
                             + s * 16 + (aq >> 1) * 8) * 2);
            #pragma unroll
            for (int jp = 0; jp < 4; jp++) {
                uint32_t bb[4];
                ldsm_x4(bb, sK + ((jp * 16 + (aq >> 1) * 8 + ar) * LDH
                                  + s * 16 + (aq & 1) * 8) * 2);
                mma_fp16(sc[2*jp],     a, bb);
                mma_fp16(sc[2*jp + 1], a, bb + 2);
            }
        }

        // ---- diagonal causal mask ----
        if (kt == qt) {
            const int lr0 = wid * 16 + gq, lr1 = lr0 + 8;
            #pragma unroll
            for (int j = 0; j < 8; j++) {
                int c = j * 8 + 2 * tig;
                if (c     > lr0) sc[j][0] = -1e30f;
                if (c + 1 > lr0) sc[j][1] = -1e30f;
                if (c     > lr1) sc[j][2] = -1e30f;
                if (c + 1 > lr1) sc[j][3] = -1e30f;
            }
        }

        // ---- online softmax ----
        float mt0 = -1e30f, mt1 = -1e30f;
        #pragma unroll
        for (int j = 0; j < 8; j++) {
            mt0 = fmaxf(mt0, fmaxf(sc[j][0], sc[j][1]));
            mt1 = fmaxf(mt1, fmaxf(sc[j][2], sc[j][3]));
        }
        mt0 = fmaxf(mt0, __shfl_xor_sync(0xffffffffu, mt0, 1));
        mt0 = fmaxf(mt0, __shfl_xor_sync(0xffffffffu, mt0, 2));
        mt1 = fmaxf(mt1, __shfl_xor_sync(0xffffffffu, mt1, 1));
        mt1 = fmaxf(mt1, __shfl_xor_sync(0xffffffffu, mt1, 2));

        float mn0 = fmaxf(m0, mt0), mn1 = fmaxf(m1, mt1);
        float al0 = __expf(m0 - mn0), al1 = __expf(m1 - mn1);
        m0 = mn0; m1 = mn1;

        uint32_t pp[8][2];
        float rs0 = 0.f, rs1 = 0.f;
        #pragma unroll
        for (int j = 0; j < 8; j++) {
            float e0 = __expf(sc[j][0] - mn0);
            float e1 = __expf(sc[j][1] - mn0);
            float e2 = __expf(sc[j][2] - mn1);
            float e3 = __expf(sc[j][3] - mn1);
            rs0 += e0 + e1; rs1 += e2 + e3;
            pp[j][0] = pack_h2(e0, e1);
            pp[j][1] = pack_h2(e2, e3);
        }
        rs0 += __shfl_xor_sync(0xffffffffu, rs0, 1);
        rs0 += __shfl_xor_sync(0xffffffffu, rs0, 2);
        rs1 += __shfl_xor_sync(0xffffffffu, rs1, 1);
        rs1 += __shfl_xor_sync(0xffffffffu, rs1, 2);
        l0 = l0 * al0 + rs0;
        l1 = l1 * al1 + rs1;

        #pragma unroll
        for (int t = 0; t < 16; t++) {
            acc[t][0] *= al0; acc[t][1] *= al0;
            acc[t][2] *= al1; acc[t][3] *= al1;
        }

        // ---- O += P V ----
        #pragma unroll
        for (int s = 0; s < 4; s++) {
            uint32_t a[4] = { pp[2*s][0], pp[2*s][1], pp[2*s+1][0], pp[2*s+1][1] };
            #pragma unroll
            for (int j2 = 0; j2 < 8; j2++) {
                uint32_t bb[4];
                ldsm_x4t(bb, sV + ((s * 16 + tr) * LDH + j2 * 16 + tc) * 2);
                mma_fp16(acc[2*j2],     a, bb);
                mma_fp16(acc[2*j2 + 1], a, bb + 2);
            }
        }
    }

    // ---- epilogue ----
    const float inv0 = 1.f / l0, inv1 = 1.f / l1;
    #pragma unroll
    for (int t = 0; t < 16; t++) {
        int row = q0 + wid * 16 + gq;
        int col = t * 8 + 2 * tig;
        *(float2*)(out + ((size_t)b * T_ + row) * H_ + col) =
            make_float2(acc[t][0] * inv0, acc[t][1] * inv0);
        *(float2*)(out + ((size_t)b * T_ + row + 8) * H_ + col) =
            make_float2(acc[t][2] * inv1, acc[t][3] * inv1);
    }
}

// ---------------------------------------------------------------------------
extern "C" void kernel_launch(void* const* d_in, const int* in_sizes, int n_in,
                              void* d_out, int out_size)
{
    const float* x  = (const float*)d_in[0];
    const float* Wk = (const float*)d_in[1];
    const float* Wq = (const float*)d_in[2];
    const float* Wv = (const float*)d_in[3];
    float* out = (float*)d_out;

    xhalf_kernel<<<(M_ * E_ / 4) / 256, 256>>>(x);
    wsplit_kernel<<<(3 * E_ * H_ + 255) / 256, 256>>>(Wk, Wq, Wv);

    const int qkv_smem = 2 * QSTG * 2;   // 2 stages * 3 tiles * bytes
    cudaFuncSetAttribute(qkv_mma_sync, cudaFuncAttributeMaxDynamicSharedMemorySize, qkv_smem);
    dim3 g1(M_ / 128, 3);
    qkv_mma_sync<<<g1, 256, qkv_smem>>>();

    cudaFuncSetAttribute(attn_mma, cudaFuncAttributeMaxDynamicSharedMemorySize, ATT_SMEM);
    dim3 g2(T_ / 64, B_);
    attn_mma<<<g2, 128, ATT_SMEM>>>(out);
}